// round 15
// baseline (speedup 1.0000x reference)
#include <cuda_runtime.h>
#include <cuda_fp16.h>
#include <cstdint>

#define BB 64
#define NP 1024
#define LL 64
#define HH 128
#define W1K 67
#define TN 128
#define NT (BB * 8)       // 512 tiles of 128 points
#define MLP_GRID 148
#define KS 136            // fp16 elements per row (272B stride)
#define H2ROW 132         // fp32 row stride for h2

__device__ float g_mlpp[MLP_GRID];   // per-CTA L2 partials (always written)
__device__ float g_chp[2 * BB];      // per-CTA chamfer partials (always written)
__device__ unsigned g_done = 0;      // self-resetting done counter

__device__ __forceinline__ float block_sum(float v, float* scratch) {
    #pragma unroll
    for (int off = 16; off; off >>= 1) v += __shfl_down_sync(0xffffffffu, v, off);
    int lane = threadIdx.x & 31, w = threadIdx.x >> 5;
    if (lane == 0) scratch[w] = v;
    __syncthreads();
    int nw = blockDim.x >> 5;
    v = (threadIdx.x < nw) ? scratch[threadIdx.x] : 0.0f;
    if (w == 0) {
        #pragma unroll
        for (int off = 16; off; off >>= 1) v += __shfl_down_sync(0xffffffffu, v, off);
    }
    return v;
}

__device__ __forceinline__ uint32_t smem_u32(const void* p) {
    uint32_t a;
    asm("{ .reg .u64 t; cvta.to.shared.u64 t, %1; cvt.u32.u64 %0, t; }"
        : "=r"(a) : "l"(p));
    return a;
}
__device__ __forceinline__ void ldmx4(uint32_t* r, uint32_t addr) {
    asm volatile("ldmatrix.sync.aligned.m8n8.x4.shared.b16 {%0,%1,%2,%3}, [%4];"
                 : "=r"(r[0]), "=r"(r[1]), "=r"(r[2]), "=r"(r[3]) : "r"(addr));
}
__device__ __forceinline__ void ldmx2(uint32_t* r, uint32_t addr) {
    asm volatile("ldmatrix.sync.aligned.m8n8.x2.shared.b16 {%0,%1}, [%2];"
                 : "=r"(r[0]), "=r"(r[1]) : "r"(addr));
}
__device__ __forceinline__ void mma_f16(float* c, const uint32_t* a,
                                        const uint32_t* b) {
    asm volatile(
        "mma.sync.aligned.m16n8k16.row.col.f32.f16.f16.f32 "
        "{%0,%1,%2,%3}, {%4,%5,%6,%7}, {%8,%9}, {%0,%1,%2,%3};"
        : "+f"(c[0]), "+f"(c[1]), "+f"(c[2]), "+f"(c[3])
        : "r"(a[0]), "r"(a[1]), "r"(a[2]), "r"(a[3]), "r"(b[0]), "r"(b[1]));
}
__device__ __forceinline__ unsigned pack_hf2(__half a, __half b) {
    return (unsigned)__half_as_ushort(a) |
           ((unsigned)__half_as_ushort(b) << 16);
}

// SMEM byte offsets (mlp)
#define OFF_W2HI 0
#define OFF_W2LO 34816
#define OFF_HHI  69632
#define OFF_H2   104448
#define OFF_W1LAT 172032       // [128][65] fp32 = 33280 B (padded, bank-clean)
#define OFF_MISC 205312

// ---------------------------------------------------------------------------
// Persistent MLP: fp16 2-product split GEMM2; W1-latent term computed inline
// per tile from SMEM-staged W1lat/b1/latent (w1l kernel folded in).
// ---------------------------------------------------------------------------
__global__ void __launch_bounds__(256) mlp_kernel(
    const float* __restrict__ pc, const float* __restrict__ pc_gt,
    const float* __restrict__ W2, const float* __restrict__ b2,
    const float* __restrict__ W1, const float* __restrict__ b1,
    const float* __restrict__ latent,
    const float* __restrict__ W3, const float* __restrict__ b3,
    float* __restrict__ out_est)
{
    extern __shared__ float smf[];
    char* sb = (char*)smf;
    __half* w2hi = (__half*)(sb + OFF_W2HI);   // [o][KS]
    __half* w2lo = (__half*)(sb + OFF_W2LO);
    __half* hhi  = (__half*)(sb + OFF_HHI);    // [n][KS]
    float* s_h2  = (float*)(sb + OFF_H2);      // [128][H2ROW]
    float* w1lat = (float*)(sb + OFF_W1LAT);   // [128][65]
    float* misc  = (float*)(sb + OFF_MISC);
    float* swx  = misc;           // [3][128]
    float* swl  = swx + 384;      // 128
    float* sb1  = swl + 128;      // 128
    float* sb2  = sb1 + 128;      // 128
    float* sw3  = sb2 + 128;      // 384
    float* sb3  = sw3 + 384;      // 4
    float* s_x  = sb3 + 4;        // [3][128]
    float* slat = s_x + 384;      // 64
    float* sred = slat + 64;      // 8

    const int tid = threadIdx.x;
    const int lane = tid & 31;
    const int wid = tid >> 5;

    // ---- one-time stage: W2 hi/lo (fp16 split), W1 both parts, biases ----
    {
        const int o = tid & 127, kh = tid >> 7;
        const float* w2r = W2 + o * HH;
        for (int k = kh * 64; k < kh * 64 + 64; k += 2) {
            float w0 = w2r[k], w1 = w2r[k + 1];
            __half h0 = __float2half_rn(w0);
            __half h1 = __float2half_rn(w1);
            *(unsigned*)&w2hi[o * KS + k] = pack_hf2(h0, h1);
            *(unsigned*)&w2lo[o * KS + k] =
                pack_hf2(__float2half_rn(w0 - __half2float(h0)),
                         __float2half_rn(w1 - __half2float(h1)));
        }
    }
    for (int i = tid; i < 128 * 64; i += 256) {
        int o = i >> 6, l = i & 63;
        w1lat[o * 65 + l] = W1[o * W1K + 3 + l];
    }
    for (int i = tid; i < 384; i += 256) {
        int k = i >> 7, o = i & 127;
        swx[k * 128 + o] = W1[o * W1K + k];
        sw3[i] = W3[i];
    }
    if (tid < 128) { sb1[tid] = b1[tid]; sb2[tid] = b2[tid]; }
    if (tid < 3) sb3[tid] = b3[tid];
    __syncthreads();

    const uint32_t u_w2hi = smem_u32(w2hi);
    const uint32_t u_w2lo = smem_u32(w2lo);
    const uint32_t u_hhi  = smem_u32(hhi);

    const int lr = lane & 7;
    const int aq = lane >> 3;
    const int arow_off = ((aq & 1) << 3) + lr;
    const int acol_off = (aq >> 1) << 3;
    const int bl15 = lane & 15;
    const int brow_off = bl15 & 7;
    const int bcol_off = (bl15 >> 3) << 3;

    const int o0 = wid * 16;
    float l2acc = 0.0f;

    for (int t = blockIdx.x; t < NT; t += MLP_GRID) {
        const int b  = t >> 3;
        const int n0 = (t & 7) * TN;

        __syncthreads();
        for (int i = tid; i < 384; i += 256) {
            int k = i >> 7, n = i & 127;
            s_x[k * 128 + n] = pc[(b * 3 + k) * NP + n0 + n];
        }
        if (tid < 64) slat[tid] = latent[b * LL + tid];
        __syncthreads();

        // ---- per-batch latent term: swl[o] = b1[o] + W1lat[o]·latent[b] ----
        if (tid < 128) {
            float acc = sb1[tid];
            const float* wr = w1lat + tid * 65;
            #pragma unroll 8
            for (int l = 0; l < 64; l++) acc = fmaf(wr[l], slat[l], acc);
            swl[tid] = acc;
        }
        __syncthreads();

        // ---- layer 1 (fp32) -> fp16 h tile [n][k] ----
        {
            const int n = tid & 127, kh = tid >> 7;
            const float x0 = s_x[n], x1 = s_x[128 + n], x2 = s_x[256 + n];
            #pragma unroll
            for (int k = kh * 64; k < kh * 64 + 64; k += 2) {
                float h0 = fmaxf(fmaf(swx[k], x0, fmaf(swx[128 + k], x1,
                             fmaf(swx[256 + k], x2, swl[k]))), 0.0f);
                float h1v = fmaxf(fmaf(swx[k + 1], x0, fmaf(swx[129 + k], x1,
                              fmaf(swx[257 + k], x2, swl[k + 1]))), 0.0f);
                *(unsigned*)&hhi[n * KS + k] =
                    pack_hf2(__float2half_rn(h0), __float2half_rn(h1v));
            }
        }
        __syncthreads();

        // ---- GEMM2: warp o-strip [o0,o0+16), fp16 2-product mma ----
        float C[16][4];
        #pragma unroll
        for (int nt = 0; nt < 16; nt++)
            #pragma unroll
            for (int j = 0; j < 4; j++) C[nt][j] = 0.0f;

        #pragma unroll
        for (int k8 = 0; k8 < 8; k8++) {
            const int k0 = k8 * 16;
            const uint32_t aoff = (uint32_t)(o0 + arow_off) * 272u +
                                  (uint32_t)(k0 + acol_off) * 2u;
            uint32_t ah[4], al[4];
            ldmx4(ah, u_w2hi + aoff);
            ldmx4(al, u_w2lo + aoff);
            #pragma unroll
            for (int nt = 0; nt < 16; nt++) {
                const uint32_t boff = (uint32_t)(nt * 8 + brow_off) * 272u +
                                      (uint32_t)(k0 + bcol_off) * 2u;
                uint32_t bh[2];
                ldmx2(bh, u_hhi + boff);
                mma_f16(C[nt], ah, bh);
                mma_f16(C[nt], al, bh);
            }
        }
        __syncthreads();

        // ---- bias + relu -> s_h2[o][n] ----
        {
            const int r = lane >> 2;
            const int cp = (lane & 3) * 2;
            const float bo  = sb2[o0 + r];
            const float bo8 = sb2[o0 + r + 8];
            #pragma unroll
            for (int nt = 0; nt < 16; nt++) {
                int n = nt * 8 + cp;
                s_h2[(o0 + r) * H2ROW + n]     = fmaxf(C[nt][0] + bo, 0.0f);
                s_h2[(o0 + r) * H2ROW + n + 1] = fmaxf(C[nt][1] + bo, 0.0f);
                s_h2[(o0 + r + 8) * H2ROW + n]     = fmaxf(C[nt][2] + bo8, 0.0f);
                s_h2[(o0 + r + 8) * H2ROW + n + 1] = fmaxf(C[nt][3] + bo8, 0.0f);
            }
        }
        __syncthreads();

        // ---- layer 3 (fp32, 3x128) + epilogue ----
        if (tid < TN) {
            int n = tid, g = n0 + n;
            float o0v = sb3[0], o1v = sb3[1], o2v = sb3[2];
            #pragma unroll 4
            for (int k = 0; k < HH; k++) {
                float hv = s_h2[k * H2ROW + n];
                o0v = fmaf(sw3[k], hv, o0v);
                o1v = fmaf(sw3[128 + k], hv, o1v);
                o2v = fmaf(sw3[256 + k], hv, o2v);
            }
            int base = (b * 3) * NP + g;
            float e0 = pc[base] - o0v;
            float e1 = pc[base + NP] - o1v;
            float e2 = pc[base + 2 * NP] - o2v;
            out_est[base] = e0;
            out_est[base + NP] = e1;
            out_est[base + 2 * NP] = e2;
            float d0 = pc_gt[base] - e0;
            float d1 = pc_gt[base + NP] - e1;
            float d2 = pc_gt[base + 2 * NP] - e2;
            l2acc += fmaf(d0, d0, fmaf(d1, d1, d2 * d2));
        }
    }

    __syncthreads();
    float s = block_sum(l2acc, sred);
    if (tid == 0) g_mlpp[blockIdx.x] = s;   // unconditional write, no init
}

// ---------------------------------------------------------------------------
// Chamfer (R8 scalar, proven): 512 thr, 4 queries/thread, split m-scan.
// Partials written unconditionally; last CTA reduces everything + writes loss.
// ---------------------------------------------------------------------------
__global__ void __launch_bounds__(512) chamfer_kernel(
    const float* __restrict__ pc_gt, const float* __restrict__ est,
    float* __restrict__ out)
{
    __shared__ float4 spts[NP];
    __shared__ float sup[256][4];
    __shared__ float sred[16];
    __shared__ int s_last;
    const int b = blockIdx.x;
    const int dir = blockIdx.y;
    const float* rows  = dir ? est   : pc_gt;
    const float* other = dir ? pc_gt : est;
    const int base = b * 3 * NP;
    const int tid  = threadIdx.x;
    const int qt   = tid & 255;
    const int half = tid >> 8;

    for (int i = tid; i < NP; i += 512) {
        float x = other[base + i];
        float y = other[base + NP + i];
        float z = other[base + 2 * NP + i];
        spts[i] = make_float4(x, y, z, fmaf(x, x, fmaf(y, y, z * z)));
    }
    __syncthreads();

    float qx[4], qy[4], qz[4], qa2[4];
    #pragma unroll
    for (int q = 0; q < 4; q++) {
        int n = qt + q * 256;
        float ax = rows[base + n];
        float ay = rows[base + NP + n];
        float az = rows[base + 2 * NP + n];
        qa2[q] = fmaf(ax, ax, fmaf(ay, ay, az * az));
        qx[q] = -2.0f * ax;
        qy[q] = -2.0f * ay;
        qz[q] = -2.0f * az;
    }

    float bst[4][2];
    #pragma unroll
    for (int q = 0; q < 4; q++) { bst[q][0] = 3.4e38f; bst[q][1] = 3.4e38f; }

    const int m0 = half * 512;
    for (int m = m0; m < m0 + 512; m += 4) {
        float4 p0 = spts[m];
        float4 p1 = spts[m + 1];
        float4 p2 = spts[m + 2];
        float4 p3 = spts[m + 3];
        #pragma unroll
        for (int q = 0; q < 4; q++) {
            float t0 = fmaf(qz[q], p0.z, fmaf(qy[q], p0.y, fmaf(qx[q], p0.x, p0.w)));
            float t1 = fmaf(qz[q], p1.z, fmaf(qy[q], p1.y, fmaf(qx[q], p1.x, p1.w)));
            float t2 = fmaf(qz[q], p2.z, fmaf(qy[q], p2.y, fmaf(qx[q], p2.x, p2.w)));
            float t3 = fmaf(qz[q], p3.z, fmaf(qy[q], p3.y, fmaf(qx[q], p3.x, p3.w)));
            bst[q][0] = fminf(bst[q][0], fminf(t0, t1));
            bst[q][1] = fminf(bst[q][1], fminf(t2, t3));
        }
    }

    if (half) {
        #pragma unroll
        for (int q = 0; q < 4; q++)
            sup[qt][q] = fminf(bst[q][0], bst[q][1]);
    }
    __syncthreads();

    float acc = 0.0f;
    if (!half) {
        #pragma unroll
        for (int q = 0; q < 4; q++) {
            float lo = fminf(bst[q][0], bst[q][1]);
            acc += qa2[q] + fminf(lo, sup[qt][q]);
        }
    }
    float s = block_sum(acc, sred);
    if (tid == 0) {
        g_chp[dir * BB + b] = s;
        __threadfence();
        unsigned d = atomicAdd(&g_done, 1u);
        s_last = (d == 2u * BB - 1u) ? 1 : 0;
    }
    __syncthreads();

    if (s_last) {
        float vch = 0.0f, vl2 = 0.0f;
        for (int i = tid; i < 2 * BB; i += 512) vch += g_chp[i];
        for (int i = tid; i < MLP_GRID; i += 512) vl2 += g_mlpp[i];
        float rch = block_sum(vch, sred);
        __syncthreads();
        float rl2 = block_sum(vl2, sred);
        if (tid == 0) {
            float ch = rch * (1.0f / (float)(BB * NP));
            float l2 = rl2 * (1.0f / (float)(BB * 3 * NP));
            out[0] = 0.1f * ch + 0.9f * l2;
            out[1] = ch;
            out[2] = l2;
            g_done = 0;   // reset for next graph replay
        }
    }
}

extern "C" void kernel_launch(void* const* d_in, const int* in_sizes, int n_in,
                              void* d_out, int out_size) {
    const float* pc    = (const float*)d_in[0];
    const float* pc_gt = (const float*)d_in[1];
    const float* lat   = (const float*)d_in[2];
    const float* W1    = (const float*)d_in[3];
    const float* b1    = (const float*)d_in[4];
    const float* W2    = (const float*)d_in[5];
    const float* b2    = (const float*)d_in[6];
    const float* W3    = (const float*)d_in[7];
    const float* b3    = (const float*)d_in[8];
    float* out = (float*)d_out;

    size_t smem_mlp = OFF_MISC + (size_t)(384 + 128 + 128 + 128 + 384 + 4 +
                                          384 + 64 + 16) * sizeof(float);
    (void)cudaFuncSetAttribute(mlp_kernel,
                               cudaFuncAttributeMaxDynamicSharedMemorySize,
                               (int)smem_mlp);

    mlp_kernel<<<MLP_GRID, 256, smem_mlp>>>(pc, pc_gt, W2, b2, W1, b1, lat,
                                            W3, b3, out + 3);
    chamfer_kernel<<<dim3(BB, 2), 512>>>(pc_gt, out + 3, out);
}

// round 16
// speedup vs baseline: 1.0576x; 1.0576x over previous
#include <cuda_runtime.h>
#include <cuda_fp16.h>
#include <cstdint>

#define BB 64
#define NP 1024
#define LL 64
#define HH 128
#define W1K 67
#define TN 128
#define NT (BB * 8)       // 512 tiles of 128 points
#define MLP_GRID 148
#define KS 136            // fp16 elements per row (272B stride)
#define H2ROW 132         // fp32 row stride for h2

__device__ float g_acc[3];
__device__ unsigned g_done;
__device__ float g_w1l[BB * HH];

// W1L precompute (latency-optimized): coalesced SMEM staging of W1's latent
// block + 2-thread-per-output split dot (chain 64 -> 32 FMA). Block 0 also
// zeroes the accumulators.
__global__ void __launch_bounds__(256) w1l_kernel(
    const float* __restrict__ latent, const float* __restrict__ W1,
    const float* __restrict__ b1)
{
    __shared__ float sW[128 * 65];   // [o][l], pad 65 (bank-clean)
    __shared__ float slat[LL];
    if (blockIdx.x == 0 && threadIdx.x < 4) {
        if (threadIdx.x < 3) g_acc[threadIdx.x] = 0.0f;
        else g_done = 0u;
    }
    const int b = blockIdx.x;
    const int tid = threadIdx.x;

    for (int i = tid; i < 128 * 64; i += 256) {
        int o = i >> 6, l = i & 63;
        sW[o * 65 + l] = W1[o * W1K + 3 + l];   // coalesced 64-float runs
    }
    if (tid < LL) slat[tid] = latent[b * LL + tid];
    __syncthreads();

    const int o = tid >> 1, hf = tid & 1;
    const float* wr = sW + o * 65 + hf * 32;
    const float* lr = slat + hf * 32;
    float acc = 0.0f;
    #pragma unroll
    for (int l = 0; l < 32; l++) acc = fmaf(wr[l], lr[l], acc);
    acc += __shfl_xor_sync(0xffffffffu, acc, 1);
    if (!hf) g_w1l[b * HH + o] = acc + b1[o];
}

__device__ __forceinline__ float block_sum(float v, float* scratch) {
    #pragma unroll
    for (int off = 16; off; off >>= 1) v += __shfl_down_sync(0xffffffffu, v, off);
    int lane = threadIdx.x & 31, w = threadIdx.x >> 5;
    if (lane == 0) scratch[w] = v;
    __syncthreads();
    int nw = blockDim.x >> 5;
    v = (threadIdx.x < nw) ? scratch[threadIdx.x] : 0.0f;
    if (w == 0) {
        #pragma unroll
        for (int off = 16; off; off >>= 1) v += __shfl_down_sync(0xffffffffu, v, off);
    }
    return v;
}

__device__ __forceinline__ uint32_t smem_u32(const void* p) {
    uint32_t a;
    asm("{ .reg .u64 t; cvta.to.shared.u64 t, %1; cvt.u32.u64 %0, t; }"
        : "=r"(a) : "l"(p));
    return a;
}
__device__ __forceinline__ void ldmx4(uint32_t* r, uint32_t addr) {
    asm volatile("ldmatrix.sync.aligned.m8n8.x4.shared.b16 {%0,%1,%2,%3}, [%4];"
                 : "=r"(r[0]), "=r"(r[1]), "=r"(r[2]), "=r"(r[3]) : "r"(addr));
}
__device__ __forceinline__ void ldmx2(uint32_t* r, uint32_t addr) {
    asm volatile("ldmatrix.sync.aligned.m8n8.x2.shared.b16 {%0,%1}, [%2];"
                 : "=r"(r[0]), "=r"(r[1]) : "r"(addr));
}
__device__ __forceinline__ void mma_f16(float* c, const uint32_t* a,
                                        const uint32_t* b) {
    asm volatile(
        "mma.sync.aligned.m16n8k16.row.col.f32.f16.f16.f32 "
        "{%0,%1,%2,%3}, {%4,%5,%6,%7}, {%8,%9}, {%0,%1,%2,%3};"
        : "+f"(c[0]), "+f"(c[1]), "+f"(c[2]), "+f"(c[3])
        : "r"(a[0]), "r"(a[1]), "r"(a[2]), "r"(a[3]), "r"(b[0]), "r"(b[1]));
}
__device__ __forceinline__ unsigned pack_hf2(__half a, __half b) {
    return (unsigned)__half_as_ushort(a) |
           ((unsigned)__half_as_ushort(b) << 16);
}

// SMEM byte offsets (mlp)
#define OFF_W2HI 0
#define OFF_W2LO 34816
#define OFF_HHI  69632
#define OFF_H2   104448
#define OFF_MISC 172032

// ---------------------------------------------------------------------------
// Persistent MLP (R14 body, best known): fp16 2-product split GEMM2.
// ---------------------------------------------------------------------------
__global__ void __launch_bounds__(256) mlp_kernel(
    const float* __restrict__ pc, const float* __restrict__ pc_gt,
    const float* __restrict__ W2, const float* __restrict__ b2,
    const float* __restrict__ W1,
    const float* __restrict__ W3, const float* __restrict__ b3,
    float* __restrict__ out_est)
{
    extern __shared__ float smf[];
    char* sb = (char*)smf;
    __half* w2hi = (__half*)(sb + OFF_W2HI);   // [o][KS]
    __half* w2lo = (__half*)(sb + OFF_W2LO);
    __half* hhi  = (__half*)(sb + OFF_HHI);    // [n][KS]
    float* s_h2 = (float*)(sb + OFF_H2);       // [128][H2ROW]
    float* misc = (float*)(sb + OFF_MISC);
    float* swx  = misc;           // [3][128]
    float* swl  = swx + 384;      // 128
    float* sb2  = swl + 128;      // 128
    float* sw3  = sb2 + 128;      // 384
    float* sb3  = sw3 + 384;      // 4
    float* s_x  = sb3 + 4;        // [3][128]
    float* sred = s_x + 384;      // 8

    const int tid = threadIdx.x;
    const int lane = tid & 31;
    const int wid = tid >> 5;

    // ---- one-time stage: W2 hi/lo (fp16 split), small weights ----
    {
        const int o = tid & 127, kh = tid >> 7;
        const float* w2r = W2 + o * HH;
        for (int k = kh * 64; k < kh * 64 + 64; k += 2) {
            float w0 = w2r[k], w1 = w2r[k + 1];
            __half h0 = __float2half_rn(w0);
            __half h1 = __float2half_rn(w1);
            *(unsigned*)&w2hi[o * KS + k] = pack_hf2(h0, h1);
            *(unsigned*)&w2lo[o * KS + k] =
                pack_hf2(__float2half_rn(w0 - __half2float(h0)),
                         __float2half_rn(w1 - __half2float(h1)));
        }
    }
    for (int i = tid; i < 384; i += 256) {
        int k = i >> 7, o = i & 127;
        swx[k * 128 + o] = W1[o * W1K + k];
        sw3[i] = W3[i];
    }
    if (tid < 128) sb2[tid] = b2[tid];
    if (tid < 3) sb3[tid] = b3[tid];
    __syncthreads();

    const uint32_t u_w2hi = smem_u32(w2hi);
    const uint32_t u_w2lo = smem_u32(w2lo);
    const uint32_t u_hhi  = smem_u32(hhi);

    const int lr = lane & 7;
    const int aq = lane >> 3;
    const int arow_off = ((aq & 1) << 3) + lr;
    const int acol_off = (aq >> 1) << 3;
    const int bl15 = lane & 15;
    const int brow_off = bl15 & 7;
    const int bcol_off = (bl15 >> 3) << 3;

    const int o0 = wid * 16;
    float l2acc = 0.0f;

    for (int t = blockIdx.x; t < NT; t += MLP_GRID) {
        const int b  = t >> 3;
        const int n0 = (t & 7) * TN;

        __syncthreads();
        for (int i = tid; i < 384; i += 256) {
            int k = i >> 7, n = i & 127;
            s_x[k * 128 + n] = pc[(b * 3 + k) * NP + n0 + n];
        }
        if (tid < 128) swl[tid] = g_w1l[b * HH + tid];
        __syncthreads();

        // ---- layer 1 (fp32) -> fp16 h tile [n][k] ----
        {
            const int n = tid & 127, kh = tid >> 7;
            const float x0 = s_x[n], x1 = s_x[128 + n], x2 = s_x[256 + n];
            #pragma unroll
            for (int k = kh * 64; k < kh * 64 + 64; k += 2) {
                float h0 = fmaxf(fmaf(swx[k], x0, fmaf(swx[128 + k], x1,
                             fmaf(swx[256 + k], x2, swl[k]))), 0.0f);
                float h1v = fmaxf(fmaf(swx[k + 1], x0, fmaf(swx[129 + k], x1,
                              fmaf(swx[257 + k], x2, swl[k + 1]))), 0.0f);
                *(unsigned*)&hhi[n * KS + k] =
                    pack_hf2(__float2half_rn(h0), __float2half_rn(h1v));
            }
        }
        __syncthreads();

        // ---- GEMM2: warp o-strip [o0,o0+16), fp16 2-product mma ----
        float C[16][4];
        #pragma unroll
        for (int nt = 0; nt < 16; nt++)
            #pragma unroll
            for (int j = 0; j < 4; j++) C[nt][j] = 0.0f;

        #pragma unroll
        for (int k8 = 0; k8 < 8; k8++) {
            const int k0 = k8 * 16;
            const uint32_t aoff = (uint32_t)(o0 + arow_off) * 272u +
                                  (uint32_t)(k0 + acol_off) * 2u;
            uint32_t ah[4], al[4];
            ldmx4(ah, u_w2hi + aoff);
            ldmx4(al, u_w2lo + aoff);
            #pragma unroll
            for (int nt = 0; nt < 16; nt++) {
                const uint32_t boff = (uint32_t)(nt * 8 + brow_off) * 272u +
                                      (uint32_t)(k0 + bcol_off) * 2u;
                uint32_t bh[2];
                ldmx2(bh, u_hhi + boff);
                mma_f16(C[nt], ah, bh);
                mma_f16(C[nt], al, bh);
            }
        }
        __syncthreads();

        // ---- bias + relu -> s_h2[o][n] ----
        {
            const int r = lane >> 2;
            const int cp = (lane & 3) * 2;
            const float bo  = sb2[o0 + r];
            const float bo8 = sb2[o0 + r + 8];
            #pragma unroll
            for (int nt = 0; nt < 16; nt++) {
                int n = nt * 8 + cp;
                s_h2[(o0 + r) * H2ROW + n]     = fmaxf(C[nt][0] + bo, 0.0f);
                s_h2[(o0 + r) * H2ROW + n + 1] = fmaxf(C[nt][1] + bo, 0.0f);
                s_h2[(o0 + r + 8) * H2ROW + n]     = fmaxf(C[nt][2] + bo8, 0.0f);
                s_h2[(o0 + r + 8) * H2ROW + n + 1] = fmaxf(C[nt][3] + bo8, 0.0f);
            }
        }
        __syncthreads();

        // ---- layer 3 (fp32, 3x128) + epilogue ----
        if (tid < TN) {
            int n = tid, g = n0 + n;
            float o0v = sb3[0], o1v = sb3[1], o2v = sb3[2];
            #pragma unroll 4
            for (int k = 0; k < HH; k++) {
                float hv = s_h2[k * H2ROW + n];
                o0v = fmaf(sw3[k], hv, o0v);
                o1v = fmaf(sw3[128 + k], hv, o1v);
                o2v = fmaf(sw3[256 + k], hv, o2v);
            }
            int base = (b * 3) * NP + g;
            float e0 = pc[base] - o0v;
            float e1 = pc[base + NP] - o1v;
            float e2 = pc[base + 2 * NP] - o2v;
            out_est[base] = e0;
            out_est[base + NP] = e1;
            out_est[base + 2 * NP] = e2;
            float d0 = pc_gt[base] - e0;
            float d1 = pc_gt[base + NP] - e1;
            float d2 = pc_gt[base + 2 * NP] - e2;
            l2acc += fmaf(d0, d0, fmaf(d1, d1, d2 * d2));
        }
    }

    __syncthreads();
    float s = block_sum(l2acc, sred);
    if (tid == 0) atomicAdd(&g_acc[2], s);
}

// ---------------------------------------------------------------------------
// Chamfer (R8 scalar, proven): 512 thr, 4 queries/thread, split m-scan.
// Last CTA to finish also writes the final loss.
// ---------------------------------------------------------------------------
__global__ void __launch_bounds__(512) chamfer_kernel(
    const float* __restrict__ pc_gt, const float* __restrict__ est,
    float* __restrict__ out)
{
    __shared__ float4 spts[NP];
    __shared__ float sup[256][4];
    __shared__ float sred[16];
    const int b = blockIdx.x;
    const int dir = blockIdx.y;
    const float* rows  = dir ? est   : pc_gt;
    const float* other = dir ? pc_gt : est;
    const int base = b * 3 * NP;
    const int tid  = threadIdx.x;
    const int qt   = tid & 255;
    const int half = tid >> 8;

    for (int i = tid; i < NP; i += 512) {
        float x = other[base + i];
        float y = other[base + NP + i];
        float z = other[base + 2 * NP + i];
        spts[i] = make_float4(x, y, z, fmaf(x, x, fmaf(y, y, z * z)));
    }
    __syncthreads();

    float qx[4], qy[4], qz[4], qa2[4];
    #pragma unroll
    for (int q = 0; q < 4; q++) {
        int n = qt + q * 256;
        float ax = rows[base + n];
        float ay = rows[base + NP + n];
        float az = rows[base + 2 * NP + n];
        qa2[q] = fmaf(ax, ax, fmaf(ay, ay, az * az));
        qx[q] = -2.0f * ax;
        qy[q] = -2.0f * ay;
        qz[q] = -2.0f * az;
    }

    float bst[4][2];
    #pragma unroll
    for (int q = 0; q < 4; q++) { bst[q][0] = 3.4e38f; bst[q][1] = 3.4e38f; }

    const int m0 = half * 512;
    for (int m = m0; m < m0 + 512; m += 4) {
        float4 p0 = spts[m];
        float4 p1 = spts[m + 1];
        float4 p2 = spts[m + 2];
        float4 p3 = spts[m + 3];
        #pragma unroll
        for (int q = 0; q < 4; q++) {
            float t0 = fmaf(qz[q], p0.z, fmaf(qy[q], p0.y, fmaf(qx[q], p0.x, p0.w)));
            float t1 = fmaf(qz[q], p1.z, fmaf(qy[q], p1.y, fmaf(qx[q], p1.x, p1.w)));
            float t2 = fmaf(qz[q], p2.z, fmaf(qy[q], p2.y, fmaf(qx[q], p2.x, p2.w)));
            float t3 = fmaf(qz[q], p3.z, fmaf(qy[q], p3.y, fmaf(qx[q], p3.x, p3.w)));
            bst[q][0] = fminf(bst[q][0], fminf(t0, t1));
            bst[q][1] = fminf(bst[q][1], fminf(t2, t3));
        }
    }

    if (half) {
        #pragma unroll
        for (int q = 0; q < 4; q++)
            sup[qt][q] = fminf(bst[q][0], bst[q][1]);
    }
    __syncthreads();

    float acc = 0.0f;
    if (!half) {
        #pragma unroll
        for (int q = 0; q < 4; q++) {
            float lo = fminf(bst[q][0], bst[q][1]);
            acc += qa2[q] + fminf(lo, sup[qt][q]);
        }
    }
    float s = block_sum(acc, sred);
    if (tid == 0) {
        atomicAdd(&g_acc[dir], s);
        __threadfence();
        unsigned d = atomicAdd(&g_done, 1u);
        if (d == 2u * BB - 1u) {
            float ch = (g_acc[0] + g_acc[1]) * (1.0f / (float)(BB * NP));
            float l2 = g_acc[2] * (1.0f / (float)(BB * 3 * NP));
            out[0] = 0.1f * ch + 0.9f * l2;
            out[1] = ch;
            out[2] = l2;
        }
    }
}

extern "C" void kernel_launch(void* const* d_in, const int* in_sizes, int n_in,
                              void* d_out, int out_size) {
    const float* pc    = (const float*)d_in[0];
    const float* pc_gt = (const float*)d_in[1];
    const float* lat   = (const float*)d_in[2];
    const float* W1    = (const float*)d_in[3];
    const float* b1    = (const float*)d_in[4];
    const float* W2    = (const float*)d_in[5];
    const float* b2    = (const float*)d_in[6];
    const float* W3    = (const float*)d_in[7];
    const float* b3    = (const float*)d_in[8];
    float* out = (float*)d_out;

    size_t smem_mlp = OFF_MISC + (size_t)(384 + 128 + 128 + 384 + 4 + 384 + 16)
                                 * sizeof(float);
    (void)cudaFuncSetAttribute(mlp_kernel,
                               cudaFuncAttributeMaxDynamicSharedMemorySize,
                               (int)smem_mlp);

    w1l_kernel<<<BB, 256>>>(lat, W1, b1);
    mlp_kernel<<<MLP_GRID, 256, smem_mlp>>>(pc, pc_gt, W2, b2, W1, W3, b3,
                                            out + 3);
    chamfer_kernel<<<dim3(BB, 2), 512>>>(pc_gt, out + 3, out);
}